// round 6
// baseline (speedup 1.0000x reference)
#include <cuda_runtime.h>
#include <math.h>

#define W 160
#define H 160
#define D 160
#define NB 2
#define PLANE (H * W)              // 25600
#define VOL (D * H * W)            // 4096000
#define NE (NB * VOL)              // 8192000
#define INV_SZ (1.0f / 125.0f)

// Fused-tile geometry
#define TX 32
#define TY 32
#define HALO_X 36
#define HALO_Y 36
#define ZC 40                      // z-chunk length
#define NZC 4                      // chunks per volume

// Scratch (__device__ globals: allocation-free rule)
__device__ float g_s1f[NE];
__device__ float g_s1m[NE];
__device__ float g_s2f[NE];
__device__ float g_s2m[NE];
__device__ double g_acc;

__device__ __forceinline__ float frsqrt_approx(float x) {
    float y;
    asm("rsqrt.approx.f32 %0, %1;" : "=f"(y) : "f"(x));
    return y;
}
__device__ __forceinline__ int clampi(int v, int lo, int hi) {
    return v < lo ? lo : (v > hi ? hi : v);
}

__global__ void k_zero_acc() { g_acc = 0.0; }

// ---------------------------------------------------------------------------
// Loaders: produce the per-voxel scalar that gets box-filtered.
struct LoadRaw {
    const float* __restrict__ p;
    __device__ __forceinline__ float operator()(int i) const { return p[i]; }
};
struct LoadG {  // (im - u)^2
    const float* __restrict__ im;
    const float* __restrict__ s1;
    __device__ __forceinline__ float operator()(int i) const {
        float d = im[i] - s1[i] * INV_SZ;
        return d * d;
    }
};
struct LoadP {  // n_F * n_M
    const float* __restrict__ f;
    const float* __restrict__ m;
    const float* __restrict__ s1f;
    const float* __restrict__ s1m;
    const float* __restrict__ s2f;
    const float* __restrict__ s2m;
    __device__ __forceinline__ float operator()(int i) const {
        float uf = s1f[i] * INV_SZ;
        float um = s1m[i] * INV_SZ;
        float vf = s2f[i] * INV_SZ;
        float vm = s2m[i] * INV_SZ;
        float pr = fmaxf(vf * vm, 1e-24f);
        return (f[i] - uf) * (m[i] - um) * frsqrt_approx(pr);
    }
};

// ---------------------------------------------------------------------------
// Compute one xy-box-summed plane for slice zp into out[4] (one value per
// thread point). Block = (32,8); thread point k lives at local y = ty + 8k.
// Exactly 2 __syncthreads per plane (see ordering argument in comments).
template <class L>
__device__ __forceinline__ void compute_plane(
    const L& ld, int n, int zp, int gx0, int gy0,
    float (*s_in)[HALO_X], float (*s_xr)[TX], float out[4])
{
    const int tid = threadIdx.y * 32 + threadIdx.x;
    const int zbase = n * VOL + zp * PLANE;

    // Load halo tile (clamped coords = replicate padding), value via loader.
    for (int i = tid; i < HALO_Y * HALO_X; i += 256) {
        int ly = i / HALO_X;
        int lx = i - ly * HALO_X;
        int gy = clampi(gy0 - 2 + ly, 0, H - 1);
        int gx = clampi(gx0 - 2 + lx, 0, W - 1);
        s_in[ly][lx] = ld(zbase + gy * W + gx);
    }
    __syncthreads();   // orders: loads done; also orders prev-iter y-box reads
                       // of s_xr before this iter's x-box writes.

    // x-box: 36 rows x 32 cols
    for (int r = threadIdx.y; r < HALO_Y; r += 8) {
        float v = s_in[r][threadIdx.x]     + s_in[r][threadIdx.x + 1]
                + s_in[r][threadIdx.x + 2] + s_in[r][threadIdx.x + 3]
                + s_in[r][threadIdx.x + 4];
        s_xr[r][threadIdx.x] = v;
    }
    __syncthreads();   // orders: x-box writes before y-box reads; also orders
                       // this iter's s_in reads before next iter's load writes.

    // y-box: each thread's 4 points
#pragma unroll
    for (int k = 0; k < 4; k++) {
        int L0 = threadIdx.y + 8 * k;
        out[k] = s_xr[L0][threadIdx.x]     + s_xr[L0 + 1][threadIdx.x]
               + s_xr[L0 + 2][threadIdx.x] + s_xr[L0 + 3][threadIdx.x]
               + s_xr[L0 + 4][threadIdx.x];
    }
}

// ---------------------------------------------------------------------------
// Fused 3D box (x+y in smem, z sliding in registers), one field per launch.
// grid = (5, 5, NZC*NB); block = (32, 8)
template <class L>
__global__ void __launch_bounds__(256) k_fused_box(L ld, float* __restrict__ out) {
    __shared__ float s_in[HALO_Y][HALO_X];
    __shared__ float s_xr[HALO_Y][TX];

    const int gx0 = blockIdx.x * TX;
    const int gy0 = blockIdx.y * TY;
    const int chunk = blockIdx.z & (NZC - 1);
    const int n = blockIdx.z >> 2;
    const int z0 = chunk * ZC;

    float p0[4], p1[4], p2[4], p3[4], p4[4];
    compute_plane(ld, n, clampi(z0 - 2, 0, D - 1), gx0, gy0, s_in, s_xr, p0);
    compute_plane(ld, n, clampi(z0 - 1, 0, D - 1), gx0, gy0, s_in, s_xr, p1);
    compute_plane(ld, n, z0,                       gx0, gy0, s_in, s_xr, p2);
    compute_plane(ld, n, clampi(z0 + 1, 0, D - 1), gx0, gy0, s_in, s_xr, p3);

    for (int z = z0; z < z0 + ZC; z++) {
        compute_plane(ld, n, clampi(z + 2, 0, D - 1), gx0, gy0, s_in, s_xr, p4);
        int ob = n * VOL + z * PLANE + gy0 * W + gx0;
#pragma unroll
        for (int k = 0; k < 4; k++) {
            float s = p0[k] + p1[k] + p2[k] + p3[k] + p4[k];
            out[ob + (threadIdx.y + 8 * k) * W + threadIdx.x] = s;
            p0[k] = p1[k]; p1[k] = p2[k]; p2[k] = p3[k]; p3[k] = p4[k];
        }
    }
}

// ---------------------------------------------------------------------------
// Stage 3: fused box(n_F*n_M) + masked -sum(cross^2) reduction. No output vol.
// grid = (5, 5, NZC*NB); block = (32, 8)
__global__ void __launch_bounds__(256) k_fused_reduce(LoadP ld,
                                                      const float* __restrict__ mask) {
    __shared__ float s_in[HALO_Y][HALO_X];
    __shared__ float s_xr[HALO_Y][TX];
    __shared__ double sred[256];

    const int gx0 = blockIdx.x * TX;
    const int gy0 = blockIdx.y * TY;
    const int chunk = blockIdx.z & (NZC - 1);
    const int n = blockIdx.z >> 2;
    const int z0 = chunk * ZC;

    float p0[4], p1[4], p2[4], p3[4], p4[4];
    compute_plane(ld, n, clampi(z0 - 2, 0, D - 1), gx0, gy0, s_in, s_xr, p0);
    compute_plane(ld, n, clampi(z0 - 1, 0, D - 1), gx0, gy0, s_in, s_xr, p1);
    compute_plane(ld, n, z0,                       gx0, gy0, s_in, s_xr, p2);
    compute_plane(ld, n, clampi(z0 + 1, 0, D - 1), gx0, gy0, s_in, s_xr, p3);

    double acc = 0.0;
    for (int z = z0; z < z0 + ZC; z++) {
        compute_plane(ld, n, clampi(z + 2, 0, D - 1), gx0, gy0, s_in, s_xr, p4);
        int ob = n * VOL + z * PLANE + gy0 * W + gx0;
#pragma unroll
        for (int k = 0; k < 4; k++) {
            float s = p0[k] + p1[k] + p2[k] + p3[k] + p4[k];
            float mk = mask[ob + (threadIdx.y + 8 * k) * W + threadIdx.x];
            acc += (double)(s * s * mk);
            p0[k] = p1[k]; p1[k] = p2[k]; p2[k] = p3[k]; p3[k] = p4[k];
        }
    }

    const int t = threadIdx.y * 32 + threadIdx.x;
    sred[t] = acc;
    __syncthreads();
    for (int s = 128; s > 0; s >>= 1) {
        if (t < s) sred[t] += sred[t + s];
        __syncthreads();
    }
    if (t == 0) atomicAdd(&g_acc, sred[0]);
}

__global__ void k_finish(float* __restrict__ out) {
    out[0] = (float)(-g_acc);
}

// ---------------------------------------------------------------------------
extern "C" void kernel_launch(void* const* d_in, const int* in_sizes, int n_in,
                              void* d_out, int out_size) {
    const float* f    = (const float*)d_in[0];
    const float* m    = (const float*)d_in[1];
    const float* mask = (const float*)d_in[2];
    float* out = (float*)d_out;

    float* s1f = nullptr; cudaGetSymbolAddress((void**)&s1f, g_s1f);
    float* s1m = nullptr; cudaGetSymbolAddress((void**)&s1m, g_s1m);
    float* s2f = nullptr; cudaGetSymbolAddress((void**)&s2f, g_s2f);
    float* s2m = nullptr; cudaGetSymbolAddress((void**)&s2m, g_s2m);

    dim3 blk(32, 8);
    dim3 grd(W / TX, H / TY, NZC * NB);   // (5, 5, 8)

    k_zero_acc<<<1, 1>>>();

    // Stage 1: u*SZ = box(im), per field
    k_fused_box<<<grd, blk>>>(LoadRaw{f}, s1f);
    k_fused_box<<<grd, blk>>>(LoadRaw{m}, s1m);

    // Stage 2: sigma^2*SZ = box((im - u)^2), per field
    k_fused_box<<<grd, blk>>>(LoadG{f, s1f}, s2f);
    k_fused_box<<<grd, blk>>>(LoadG{m, s1m}, s2m);

    // Stage 3: box(n_F * n_M) fused with -sum(cross^2 * mask)
    k_fused_reduce<<<grd, blk>>>(LoadP{f, m, s1f, s1m, s2f, s2m}, mask);

    k_finish<<<1, 1>>>(out);
    (void)in_sizes; (void)n_in; (void)out_size;
}

// round 7
// speedup vs baseline: 3.5637x; 3.5637x over previous
#include <cuda_runtime.h>
#include <math.h>

#define W 160
#define H 160
#define D 160
#define NB 2
#define PLANE (H * W)              // 25600
#define VOL (D * H * W)            // 4096000
#define NE (NB * VOL)              // 8192000
#define INV_SZ (1.0f / 125.0f)

// xy tile geometry
#define TX 32
#define TY 32
#define HX 36
#define HY 36

// z sliding-pass decomposition: 160 = 5 chunks of 32
#define NCHUNK 5
#define CHUNK 32
#define NCOL (NB * 160 * 160)          // 51200 columns
#define SLIDE_THREADS (NCOL * NCHUNK)  // 256000

// Scratch (__device__ globals: allocation-free rule)
__device__ float g_s1f[NE];
__device__ float g_s1m[NE];
__device__ float g_s2f[NE];
__device__ float g_s2m[NE];
__device__ float g_t0[NE];
__device__ float g_t1[NE];
__device__ double g_acc;

__device__ __forceinline__ float frsqrt_approx(float x) {
    float y;
    asm("rsqrt.approx.f32 %0, %1;" : "=f"(y) : "f"(x));
    return y;
}
__device__ __forceinline__ int clampi(int v, int lo, int hi) {
    return v < lo ? lo : (v > hi ? hi : v);
}

__global__ void k_zero_acc() { g_acc = 0.0; }

// ---------------------------------------------------------------------------
// Loaders
struct LoadRaw {
    const float* __restrict__ p;
    __device__ __forceinline__ float operator()(int i) const { return p[i]; }
};
struct LoadG {  // (im - u)^2
    const float* __restrict__ im;
    const float* __restrict__ s1;
    __device__ __forceinline__ float operator()(int i) const {
        float d = im[i] - s1[i] * INV_SZ;
        return d * d;
    }
};
struct LoadP {  // n_F * n_M
    const float* __restrict__ f;
    const float* __restrict__ m;
    const float* __restrict__ s1f;
    const float* __restrict__ s1m;
    const float* __restrict__ s2f;
    const float* __restrict__ s2m;
    __device__ __forceinline__ float operator()(int i) const {
        float uf = s1f[i] * INV_SZ;
        float um = s1m[i] * INV_SZ;
        float vf = s2f[i] * INV_SZ;
        float vm = s2m[i] * INV_SZ;
        float pr = fmaxf(vf * vm, 1e-24f);
        return (f[i] - uf) * (m[i] - um) * frsqrt_approx(pr);
    }
};

// ---------------------------------------------------------------------------
// xy box-sum of one 32x32 tile of one z-plane, two fields per launch.
// grid = (5, 5, D*NB), block = (32, 8). One plane per block: no serialization.
template <class LA, class LB>
__global__ void __launch_bounds__(256) k_xy_pair(LA la, LB lb,
                                                 float* __restrict__ oa,
                                                 float* __restrict__ ob) {
    __shared__ float sa_in[HY][HX];
    __shared__ float sb_in[HY][HX];
    __shared__ float sa_xr[HY][TX];
    __shared__ float sb_xr[HY][TX];

    const int gx0 = blockIdx.x * TX;
    const int gy0 = blockIdx.y * TY;
    const int zp  = blockIdx.z % D;
    const int n   = blockIdx.z / D;
    const int zbase = n * VOL + zp * PLANE;
    const int tid = threadIdx.y * 32 + threadIdx.x;

    // Halo load (replicate padding via clamped coords)
    for (int i = tid; i < HY * HX; i += 256) {
        int ly = i / HX;
        int lx = i - ly * HX;
        int gy = clampi(gy0 - 2 + ly, 0, H - 1);
        int gx = clampi(gx0 - 2 + lx, 0, W - 1);
        int j = zbase + gy * W + gx;
        sa_in[ly][lx] = la(j);
        sb_in[ly][lx] = lb(j);
    }
    __syncthreads();

    // x-box: 36 rows x 32 cols
    for (int r = threadIdx.y; r < HY; r += 8) {
        int x = threadIdx.x;
        sa_xr[r][x] = sa_in[r][x] + sa_in[r][x+1] + sa_in[r][x+2]
                    + sa_in[r][x+3] + sa_in[r][x+4];
        sb_xr[r][x] = sb_in[r][x] + sb_in[r][x+1] + sb_in[r][x+2]
                    + sb_in[r][x+3] + sb_in[r][x+4];
    }
    __syncthreads();

    // y-box + store: each thread 4 output rows
    const int ob_base = zbase + gy0 * W + gx0;
#pragma unroll
    for (int k = 0; k < 4; k++) {
        int L0 = threadIdx.y + 8 * k;
        int x = threadIdx.x;
        float va = sa_xr[L0][x] + sa_xr[L0+1][x] + sa_xr[L0+2][x]
                 + sa_xr[L0+3][x] + sa_xr[L0+4][x];
        float vb = sb_xr[L0][x] + sb_xr[L0+1][x] + sb_xr[L0+2][x]
                 + sb_xr[L0+3][x] + sb_xr[L0+4][x];
        int o = ob_base + L0 * W + x;
        oa[o] = va;
        ob[o] = vb;
    }
}

// Single-field xy kernel (stage 3 front)
template <class L>
__global__ void __launch_bounds__(256) k_xy_one(L ld, float* __restrict__ oa) {
    __shared__ float s_in[HY][HX];
    __shared__ float s_xr[HY][TX];

    const int gx0 = blockIdx.x * TX;
    const int gy0 = blockIdx.y * TY;
    const int zp  = blockIdx.z % D;
    const int n   = blockIdx.z / D;
    const int zbase = n * VOL + zp * PLANE;
    const int tid = threadIdx.y * 32 + threadIdx.x;

    for (int i = tid; i < HY * HX; i += 256) {
        int ly = i / HX;
        int lx = i - ly * HX;
        int gy = clampi(gy0 - 2 + ly, 0, H - 1);
        int gx = clampi(gx0 - 2 + lx, 0, W - 1);
        s_in[ly][lx] = ld(zbase + gy * W + gx);
    }
    __syncthreads();

    for (int r = threadIdx.y; r < HY; r += 8) {
        int x = threadIdx.x;
        s_xr[r][x] = s_in[r][x] + s_in[r][x+1] + s_in[r][x+2]
                   + s_in[r][x+3] + s_in[r][x+4];
    }
    __syncthreads();

    const int ob_base = zbase + gy0 * W + gx0;
#pragma unroll
    for (int k = 0; k < 4; k++) {
        int L0 = threadIdx.y + 8 * k;
        int x = threadIdx.x;
        float v = s_xr[L0][x] + s_xr[L0+1][x] + s_xr[L0+2][x]
                + s_xr[L0+3][x] + s_xr[L0+4][x];
        oa[ob_base + L0 * W + x] = v;
    }
}

// ---------------------------------------------------------------------------
// z-axis sliding 5-tap clamped sum, two fields (proven in R2 build).
// elemStride = PLANE, column fixed (n, y, x).
__global__ void k_slide_pair_z(const float* __restrict__ a, const float* __restrict__ b,
                               float* __restrict__ oa, float* __restrict__ ob) {
    int tid = blockIdx.x * blockDim.x + threadIdx.x;
    if (tid >= SLIDE_THREADS) return;
    int c = tid % NCOL;
    int chunk = tid / NCOL;
    int x = c % W;
    int y = (c / W) % 160;
    int n = c / (160 * W);
    int base = n * VOL + y * W + x;
    int z0 = chunk * CHUNK;

    float sa = 0.f, sb = 0.f;
#pragma unroll
    for (int d = -2; d <= 2; d++) {
        int zz = clampi(z0 + d, 0, 159);
        sa += a[base + zz * PLANE];
        sb += b[base + zz * PLANE];
    }
#pragma unroll 4
    for (int j = 0; j < CHUNK; j++) {
        int z = z0 + j;
        oa[base + z * PLANE] = sa;
        ob[base + z * PLANE] = sb;
        int zn = z + 3 > 159 ? 159 : z + 3;
        int zo = z - 2 < 0 ? 0 : z - 2;
        sa += a[base + zn * PLANE] - a[base + zo * PLANE];
        sb += b[base + zn * PLANE] - b[base + zo * PLANE];
    }
}

// Final z-pass fused with masked -sum(cross^2) reduction (proven in R2 build).
__global__ void k_slide_reduce(const float* __restrict__ a, const float* __restrict__ mask) {
    __shared__ double sdata[256];
    int tid = blockIdx.x * blockDim.x + threadIdx.x;
    double acc = 0.0;
    if (tid < SLIDE_THREADS) {
        int c = tid % NCOL;
        int chunk = tid / NCOL;
        int x = c % W;
        int y = (c / W) % 160;
        int n = c / (160 * W);
        int base = n * VOL + y * W + x;
        int z0 = chunk * CHUNK;

        float sa = 0.f;
#pragma unroll
        for (int d = -2; d <= 2; d++) {
            int zz = clampi(z0 + d, 0, 159);
            sa += a[base + zz * PLANE];
        }
#pragma unroll 4
        for (int j = 0; j < CHUNK; j++) {
            int z = z0 + j;
            float cross = sa;
            acc += (double)(cross * cross * mask[base + z * PLANE]);
            int zn = z + 3 > 159 ? 159 : z + 3;
            int zo = z - 2 < 0 ? 0 : z - 2;
            sa += a[base + zn * PLANE] - a[base + zo * PLANE];
        }
    }
    int t = threadIdx.x;
    sdata[t] = acc;
    __syncthreads();
    for (int s = 128; s > 0; s >>= 1) {
        if (t < s) sdata[t] += sdata[t + s];
        __syncthreads();
    }
    if (t == 0) atomicAdd(&g_acc, sdata[0]);
}

__global__ void k_finish(float* __restrict__ out) {
    out[0] = (float)(-g_acc);
}

// ---------------------------------------------------------------------------
extern "C" void kernel_launch(void* const* d_in, const int* in_sizes, int n_in,
                              void* d_out, int out_size) {
    const float* f    = (const float*)d_in[0];
    const float* m    = (const float*)d_in[1];
    const float* mask = (const float*)d_in[2];
    float* out = (float*)d_out;

    float* s1f = nullptr; cudaGetSymbolAddress((void**)&s1f, g_s1f);
    float* s1m = nullptr; cudaGetSymbolAddress((void**)&s1m, g_s1m);
    float* s2f = nullptr; cudaGetSymbolAddress((void**)&s2f, g_s2f);
    float* s2m = nullptr; cudaGetSymbolAddress((void**)&s2m, g_s2m);
    float* t0  = nullptr; cudaGetSymbolAddress((void**)&t0, g_t0);
    float* t1  = nullptr; cudaGetSymbolAddress((void**)&t1, g_t1);

    dim3 blk(32, 8);
    dim3 grd(W / TX, H / TY, D * NB);   // (5, 5, 320) = 8000 blocks
    const int TB = 256;
    const int gridS = (SLIDE_THREADS + TB - 1) / TB; // 1000

    k_zero_acc<<<1, 1>>>();

    // Stage 1: xy box of F, M, then z slide -> s1
    k_xy_pair<<<grd, blk>>>(LoadRaw{f}, LoadRaw{m}, t0, t1);
    k_slide_pair_z<<<gridS, TB>>>(t0, t1, s1f, s1m);

    // Stage 2: xy box of (im-u)^2, then z slide -> s2
    k_xy_pair<<<grd, blk>>>(LoadG{f, s1f}, LoadG{m, s1m}, t0, t1);
    k_slide_pair_z<<<gridS, TB>>>(t0, t1, s2f, s2m);

    // Stage 3: xy box of n_F*n_M, then z slide + masked reduction
    k_xy_one<<<grd, blk>>>(LoadP{f, m, s1f, s1m, s2f, s2m}, t0);
    k_slide_reduce<<<gridS, TB>>>(t0, mask);

    k_finish<<<1, 1>>>(out);
    (void)in_sizes; (void)n_in; (void)out_size;
}

// round 11
// speedup vs baseline: 4.6946x; 1.3173x over previous
#include <cuda_runtime.h>
#include <cuda_fp16.h>
#include <math.h>

#define W 160
#define H 160
#define D 160
#define NB 2
#define PLANE (H * W)              // 25600
#define VOL (D * H * W)            // 4096000
#define NE (NB * VOL)              // 8192000
#define INV_SZ (1.0f / 125.0f)

// xy tile geometry
#define TX 32
#define TY 32
#define HX 36
#define HY 36

// z sliding-pass decomposition: 160 = 5 chunks of 32
#define CHUNK 32
#define NCOL (NB * 160 * 160)          // 51200 columns
#define SLIDE_THREADS (NCOL * 5)       // 256000

// Scratch (__device__ globals: allocation-free rule). fp16, pair-packed.
__device__ __half2 g_t01[NE];   // ping buffer: xy-boxed pair
__device__ __half2 g_s1[NE];    // box(F), box(M)
__device__ __half2 g_s2[NE];    // box(gF), box(gM)
__device__ __half  g_t2[NE];    // stage-3 xy-boxed product
__device__ double g_acc;

__device__ __forceinline__ float frsqrt_approx(float x) {
    float y;
    asm("rsqrt.approx.f32 %0, %1;" : "=f"(y) : "f"(x));
    return y;
}
__device__ __forceinline__ int clampi(int v, int lo, int hi) {
    return v < lo ? lo : (v > hi ? hi : v);
}
__device__ __forceinline__ float2 f2add(float2 a, float2 b) {
    return make_float2(a.x + b.x, a.y + b.y);
}
__device__ __forceinline__ float2 f2sub(float2 a, float2 b) {
    return make_float2(a.x - b.x, a.y - b.y);
}

__global__ void k_zero_acc() { g_acc = 0.0; }

// ---------------------------------------------------------------------------
// Loaders (all compute in fp32; fp16 only at global boundaries)
struct LoadRawPair {
    const float* __restrict__ f;
    const float* __restrict__ m;
    __device__ __forceinline__ float2 operator()(int i) const {
        return make_float2(f[i], m[i]);
    }
};
struct LoadGPair {  // ((f-uF)^2, (m-uM)^2)
    const float* __restrict__ f;
    const float* __restrict__ m;
    const __half2* __restrict__ s1;
    __device__ __forceinline__ float2 operator()(int i) const {
        float2 u = __half22float2(s1[i]);
        float df = f[i] - u.x * INV_SZ;
        float dm = m[i] - u.y * INV_SZ;
        return make_float2(df * df, dm * dm);
    }
};
struct LoadP {  // n_F * n_M
    const float* __restrict__ f;
    const float* __restrict__ m;
    const __half2* __restrict__ s1;
    const __half2* __restrict__ s2;
    __device__ __forceinline__ float operator()(int i) const {
        float2 u = __half22float2(s1[i]);
        float2 v = __half22float2(s2[i]);
        float pr = fmaxf((v.x * INV_SZ) * (v.y * INV_SZ), 1e-24f);
        return (f[i] - u.x * INV_SZ) * (m[i] - u.y * INV_SZ) * frsqrt_approx(pr);
    }
};

// ---------------------------------------------------------------------------
// xy box-sum of one 32x32 tile of one z-plane, pair of fields, half2 output.
// grid = (5, 5, D*NB), block = (32, 8).
template <class L>
__global__ void __launch_bounds__(256) k_xy_pair(L ld, __half2* __restrict__ out) {
    __shared__ float2 s_in[HY][HX];
    __shared__ float2 s_xr[HY][TX];

    const int gx0 = blockIdx.x * TX;
    const int gy0 = blockIdx.y * TY;
    const int zp  = blockIdx.z % D;
    const int n   = blockIdx.z / D;
    const int zbase = n * VOL + zp * PLANE;
    const int tid = threadIdx.y * 32 + threadIdx.x;

    // Halo load (replicate padding via clamped coords)
    for (int i = tid; i < HY * HX; i += 256) {
        int ly = i / HX;
        int lx = i - ly * HX;
        int gy = clampi(gy0 - 2 + ly, 0, H - 1);
        int gx = clampi(gx0 - 2 + lx, 0, W - 1);
        s_in[ly][lx] = ld(zbase + gy * W + gx);
    }
    __syncthreads();

    // x-box
    for (int r = threadIdx.y; r < HY; r += 8) {
        int x = threadIdx.x;
        float2 v = f2add(f2add(f2add(f2add(s_in[r][x], s_in[r][x+1]),
                                     s_in[r][x+2]), s_in[r][x+3]), s_in[r][x+4]);
        s_xr[r][x] = v;
    }
    __syncthreads();

    // y-box + half2 store
    const int ob_base = zbase + gy0 * W + gx0;
#pragma unroll
    for (int k = 0; k < 4; k++) {
        int L0 = threadIdx.y + 8 * k;
        int x = threadIdx.x;
        float2 va = f2add(f2add(f2add(f2add(s_xr[L0][x], s_xr[L0+1][x]),
                                      s_xr[L0+2][x]), s_xr[L0+3][x]), s_xr[L0+4][x]);
        out[ob_base + L0 * W + x] = __float22half2_rn(va);
    }
}

// Single-field xy kernel (stage 3 front), half output.
template <class L>
__global__ void __launch_bounds__(256) k_xy_one(L ld, __half* __restrict__ out) {
    __shared__ float s_in[HY][HX];
    __shared__ float s_xr[HY][TX];

    const int gx0 = blockIdx.x * TX;
    const int gy0 = blockIdx.y * TY;
    const int zp  = blockIdx.z % D;
    const int n   = blockIdx.z / D;
    const int zbase = n * VOL + zp * PLANE;
    const int tid = threadIdx.y * 32 + threadIdx.x;

    for (int i = tid; i < HY * HX; i += 256) {
        int ly = i / HX;
        int lx = i - ly * HX;
        int gy = clampi(gy0 - 2 + ly, 0, H - 1);
        int gx = clampi(gx0 - 2 + lx, 0, W - 1);
        s_in[ly][lx] = ld(zbase + gy * W + gx);
    }
    __syncthreads();

    for (int r = threadIdx.y; r < HY; r += 8) {
        int x = threadIdx.x;
        s_xr[r][x] = s_in[r][x] + s_in[r][x+1] + s_in[r][x+2]
                   + s_in[r][x+3] + s_in[r][x+4];
    }
    __syncthreads();

    const int ob_base = zbase + gy0 * W + gx0;
#pragma unroll
    for (int k = 0; k < 4; k++) {
        int L0 = threadIdx.y + 8 * k;
        int x = threadIdx.x;
        float v = s_xr[L0][x] + s_xr[L0+1][x] + s_xr[L0+2][x]
                + s_xr[L0+3][x] + s_xr[L0+4][x];
        out[ob_base + L0 * W + x] = __float2half_rn(v);
    }
}

// ---------------------------------------------------------------------------
// z-axis sliding 5-tap clamped sum, half2 in/out, float2 accumulation.
__global__ void k_slide_pair_z(const __half2* __restrict__ a, __half2* __restrict__ o) {
    int tid = blockIdx.x * blockDim.x + threadIdx.x;
    if (tid >= SLIDE_THREADS) return;
    int c = tid % NCOL;
    int chunk = tid / NCOL;
    int x = c % W;
    int y = (c / W) % 160;
    int n = c / (160 * W);
    int base = n * VOL + y * W + x;
    int z0 = chunk * CHUNK;

    float2 s = make_float2(0.f, 0.f);
#pragma unroll
    for (int d = -2; d <= 2; d++) {
        int zz = clampi(z0 + d, 0, 159);
        s = f2add(s, __half22float2(a[base + zz * PLANE]));
    }
#pragma unroll 4
    for (int j = 0; j < CHUNK; j++) {
        int z = z0 + j;
        o[base + z * PLANE] = __float22half2_rn(s);
        int zn = z + 3 > 159 ? 159 : z + 3;
        int zo = z - 2 < 0 ? 0 : z - 2;
        s = f2add(s, f2sub(__half22float2(a[base + zn * PLANE]),
                           __half22float2(a[base + zo * PLANE])));
    }
}

// Final z-pass fused with masked -sum(cross^2) reduction, half input.
__global__ void k_slide_reduce(const __half* __restrict__ a,
                               const float* __restrict__ mask) {
    __shared__ double sdata[256];
    int tid = blockIdx.x * blockDim.x + threadIdx.x;
    double acc = 0.0;
    if (tid < SLIDE_THREADS) {
        int c = tid % NCOL;
        int chunk = tid / NCOL;
        int x = c % W;
        int y = (c / W) % 160;
        int n = c / (160 * W);
        int base = n * VOL + y * W + x;
        int z0 = chunk * CHUNK;

        float sa = 0.f;
#pragma unroll
        for (int d = -2; d <= 2; d++) {
            int zz = clampi(z0 + d, 0, 159);
            sa += __half2float(a[base + zz * PLANE]);
        }
#pragma unroll 4
        for (int j = 0; j < CHUNK; j++) {
            int z = z0 + j;
            acc += (double)(sa * sa * mask[base + z * PLANE]);
            int zn = z + 3 > 159 ? 159 : z + 3;
            int zo = z - 2 < 0 ? 0 : z - 2;
            sa += __half2float(a[base + zn * PLANE])
                - __half2float(a[base + zo * PLANE]);
        }
    }
    int t = threadIdx.x;
    sdata[t] = acc;
    __syncthreads();
    for (int s = 128; s > 0; s >>= 1) {
        if (t < s) sdata[t] += sdata[t + s];
        __syncthreads();
    }
    if (t == 0) atomicAdd(&g_acc, sdata[0]);
}

__global__ void k_finish(float* __restrict__ out) {
    out[0] = (float)(-g_acc);
}

// ---------------------------------------------------------------------------
extern "C" void kernel_launch(void* const* d_in, const int* in_sizes, int n_in,
                              void* d_out, int out_size) {
    const float* f    = (const float*)d_in[0];
    const float* m    = (const float*)d_in[1];
    const float* mask = (const float*)d_in[2];
    float* out = (float*)d_out;

    __half2* t01 = nullptr; cudaGetSymbolAddress((void**)&t01, g_t01);
    __half2* s1  = nullptr; cudaGetSymbolAddress((void**)&s1, g_s1);
    __half2* s2  = nullptr; cudaGetSymbolAddress((void**)&s2, g_s2);
    __half*  t2  = nullptr; cudaGetSymbolAddress((void**)&t2, g_t2);

    dim3 blk(32, 8);
    dim3 grd(W / TX, H / TY, D * NB);   // (5, 5, 320) = 8000 blocks
    const int TB = 256;
    const int gridS = (SLIDE_THREADS + TB - 1) / TB; // 1000

    k_zero_acc<<<1, 1>>>();

    // Stage 1: xy box of (F, M), then z slide -> s1
    k_xy_pair<<<grd, blk>>>(LoadRawPair{f, m}, t01);
    k_slide_pair_z<<<gridS, TB>>>(t01, s1);

    // Stage 2: xy box of ((im-u)^2 pair), then z slide -> s2
    k_xy_pair<<<grd, blk>>>(LoadGPair{f, m, s1}, t01);
    k_slide_pair_z<<<gridS, TB>>>(t01, s2);

    // Stage 3: xy box of n_F*n_M, then z slide + masked reduction
    k_xy_one<<<grd, blk>>>(LoadP{f, m, s1, s2}, t2);
    k_slide_reduce<<<gridS, TB>>>(t2, mask);

    k_finish<<<1, 1>>>(out);
    (void)in_sizes; (void)n_in; (void)out_size;
}

// round 12
// speedup vs baseline: 4.9447x; 1.0533x over previous
#include <cuda_runtime.h>
#include <cuda_fp16.h>
#include <math.h>

#define W 160
#define H 160
#define D 160
#define NB 2
#define PLANE (H * W)              // 25600
#define VOL (D * H * W)            // 4096000
#define NE (NB * VOL)              // 8192000
#define INV_SZ (1.0f / 125.0f)

// xy tile geometry
#define TX 32
#define TY 32
#define HX 36
#define HY 36

// z sliding-pass decomposition: 160 = 5 chunks of 32
#define CHUNK 32
#define NCOL (NB * 160 * 160)          // 51200 columns
#define SLIDE_THREADS (NCOL * 5)       // 256000

// Scratch (__device__ globals: allocation-free rule). fp16, pair-packed.
__device__ __half2 g_t01[NE];   // ping buffer: xy-boxed pair
__device__ __half2 g_s1[NE];    // box(F), box(M)
__device__ __half2 g_s2[NE];    // box(gF), box(gM)
__device__ __half  g_t2[NE];    // stage-3 xy-boxed product
__device__ double g_acc;

__device__ __forceinline__ float frsqrt_approx(float x) {
    float y;
    asm("rsqrt.approx.f32 %0, %1;" : "=f"(y) : "f"(x));
    return y;
}
__device__ __forceinline__ int clampi(int v, int lo, int hi) {
    return v < lo ? lo : (v > hi ? hi : v);
}
__device__ __forceinline__ float2 f2add(float2 a, float2 b) {
    return make_float2(a.x + b.x, a.y + b.y);
}
__device__ __forceinline__ float2 f2sub(float2 a, float2 b) {
    return make_float2(a.x - b.x, a.y - b.y);
}

__global__ void k_zero_acc() { g_acc = 0.0; }

// ---------------------------------------------------------------------------
// Loaders (all compute in fp32; fp16 only at global boundaries)
struct LoadRawPair {
    const float* __restrict__ f;
    const float* __restrict__ m;
    __device__ __forceinline__ float2 operator()(int i) const {
        return make_float2(f[i], m[i]);
    }
};
struct LoadGPair {  // ((f-uF)^2, (m-uM)^2)
    const float* __restrict__ f;
    const float* __restrict__ m;
    const __half2* __restrict__ s1;
    __device__ __forceinline__ float2 operator()(int i) const {
        float2 u = __half22float2(s1[i]);
        float df = f[i] - u.x * INV_SZ;
        float dm = m[i] - u.y * INV_SZ;
        return make_float2(df * df, dm * dm);
    }
};
struct LoadP {  // n_F * n_M
    const float* __restrict__ f;
    const float* __restrict__ m;
    const __half2* __restrict__ s1;
    const __half2* __restrict__ s2;
    __device__ __forceinline__ float operator()(int i) const {
        float2 u = __half22float2(s1[i]);
        float2 v = __half22float2(s2[i]);
        float pr = fmaxf((v.x * INV_SZ) * (v.y * INV_SZ), 1e-24f);
        return (f[i] - u.x * INV_SZ) * (m[i] - u.y * INV_SZ) * frsqrt_approx(pr);
    }
};

// ---------------------------------------------------------------------------
// xy box-sum of one 32x32 tile of one z-plane, pair of fields, half2 output.
// Register-sliding y-box then x-box: ~2x less smem traffic than naive 5-tap.
// grid = (5, 5, D*NB), block = 256 flat.
template <class L>
__global__ void __launch_bounds__(256) k_xy_pair(L ld, __half2* __restrict__ out) {
    __shared__ float2 s_in[HY][HX + 1];   // +1 pad
    __shared__ float2 s_yr[HX][TY + 1];   // transposed [x][y], +1 pad

    const int gx0 = blockIdx.x * TX;
    const int gy0 = blockIdx.y * TY;
    const int zp  = blockIdx.z % D;
    const int n   = blockIdx.z / D;
    const int zbase = n * VOL + zp * PLANE;
    const int tid = threadIdx.x;

    // Halo load (replicate padding via clamped coords)
    for (int i = tid; i < HY * HX; i += 256) {
        int ly = i / HX;
        int lx = i - ly * HX;
        int gy = clampi(gy0 - 2 + ly, 0, H - 1);
        int gx = clampi(gx0 - 2 + lx, 0, W - 1);
        s_in[ly][lx] = ld(zbase + gy * W + gx);
    }
    __syncthreads();

    // Phase A: y-box for all 36 halo columns; 4 consecutive y per group,
    // register sliding (8 reads / 4 outputs). 36*8 = 288 groups.
    for (int g = tid; g < HX * 8; g += 256) {
        int x = g % HX;
        int y0 = (g / HX) * 4;
        float2 s = f2add(f2add(f2add(f2add(s_in[y0][x], s_in[y0 + 1][x]),
                                     s_in[y0 + 2][x]), s_in[y0 + 3][x]), s_in[y0 + 4][x]);
        s_yr[x][y0] = s;
#pragma unroll
        for (int j = 1; j < 4; j++) {
            s = f2add(s, f2sub(s_in[y0 + 4 + j][x], s_in[y0 + j - 1][x]));
            s_yr[x][y0 + j] = s;
        }
    }
    __syncthreads();

    // Phase B: x-box; thread handles 4 consecutive x of one row, sliding.
    // tid = yrow*8 + xg so a warp covers 4 full rows -> coalesced 16B stores.
    {
        int xg = tid % 8;
        int yrow = tid / 8;
        int x0 = 4 * xg;
        float2 s = f2add(f2add(f2add(f2add(s_yr[x0][yrow], s_yr[x0 + 1][yrow]),
                                     s_yr[x0 + 2][yrow]), s_yr[x0 + 3][yrow]),
                         s_yr[x0 + 4][yrow]);
        __align__(16) __half2 r[4];
        r[0] = __float22half2_rn(s);
#pragma unroll
        for (int j = 1; j < 4; j++) {
            s = f2add(s, f2sub(s_yr[x0 + 4 + j][yrow], s_yr[x0 + j - 1][yrow]));
            r[j] = __float22half2_rn(s);
        }
        int o = zbase + (gy0 + yrow) * W + gx0 + x0;
        *reinterpret_cast<uint4*>(&out[o]) = *reinterpret_cast<uint4*>(r);
    }
}

// Single-field xy kernel (stage 3 front), half output, same structure.
template <class L>
__global__ void __launch_bounds__(256) k_xy_one(L ld, __half* __restrict__ out) {
    __shared__ float s_in[HY][HX + 1];
    __shared__ float s_yr[HX][TY + 1];

    const int gx0 = blockIdx.x * TX;
    const int gy0 = blockIdx.y * TY;
    const int zp  = blockIdx.z % D;
    const int n   = blockIdx.z / D;
    const int zbase = n * VOL + zp * PLANE;
    const int tid = threadIdx.x;

    for (int i = tid; i < HY * HX; i += 256) {
        int ly = i / HX;
        int lx = i - ly * HX;
        int gy = clampi(gy0 - 2 + ly, 0, H - 1);
        int gx = clampi(gx0 - 2 + lx, 0, W - 1);
        s_in[ly][lx] = ld(zbase + gy * W + gx);
    }
    __syncthreads();

    for (int g = tid; g < HX * 8; g += 256) {
        int x = g % HX;
        int y0 = (g / HX) * 4;
        float s = s_in[y0][x] + s_in[y0 + 1][x] + s_in[y0 + 2][x]
                + s_in[y0 + 3][x] + s_in[y0 + 4][x];
        s_yr[x][y0] = s;
#pragma unroll
        for (int j = 1; j < 4; j++) {
            s += s_in[y0 + 4 + j][x] - s_in[y0 + j - 1][x];
            s_yr[x][y0 + j] = s;
        }
    }
    __syncthreads();

    {
        int xg = tid % 8;
        int yrow = tid / 8;
        int x0 = 4 * xg;
        float s = s_yr[x0][yrow] + s_yr[x0 + 1][yrow] + s_yr[x0 + 2][yrow]
                + s_yr[x0 + 3][yrow] + s_yr[x0 + 4][yrow];
        __align__(8) __half r[4];
        r[0] = __float2half_rn(s);
#pragma unroll
        for (int j = 1; j < 4; j++) {
            s += s_yr[x0 + 4 + j][yrow] - s_yr[x0 + j - 1][yrow];
            r[j] = __float2half_rn(s);
        }
        int o = zbase + (gy0 + yrow) * W + gx0 + x0;
        *reinterpret_cast<uint2*>(&out[o]) = *reinterpret_cast<uint2*>(r);
    }
}

// ---------------------------------------------------------------------------
// z-axis sliding 5-tap clamped sum, half2 in/out, float2 accumulation.
__global__ void k_slide_pair_z(const __half2* __restrict__ a, __half2* __restrict__ o) {
    int tid = blockIdx.x * blockDim.x + threadIdx.x;
    if (tid >= SLIDE_THREADS) return;
    int c = tid % NCOL;
    int chunk = tid / NCOL;
    int x = c % W;
    int y = (c / W) % 160;
    int n = c / (160 * W);
    int base = n * VOL + y * W + x;
    int z0 = chunk * CHUNK;

    float2 s = make_float2(0.f, 0.f);
#pragma unroll
    for (int d = -2; d <= 2; d++) {
        int zz = clampi(z0 + d, 0, 159);
        s = f2add(s, __half22float2(a[base + zz * PLANE]));
    }
#pragma unroll 4
    for (int j = 0; j < CHUNK; j++) {
        int z = z0 + j;
        o[base + z * PLANE] = __float22half2_rn(s);
        int zn = z + 3 > 159 ? 159 : z + 3;
        int zo = z - 2 < 0 ? 0 : z - 2;
        s = f2add(s, f2sub(__half22float2(a[base + zn * PLANE]),
                           __half22float2(a[base + zo * PLANE])));
    }
}

// Final z-pass fused with masked -sum(cross^2) reduction, half input.
__global__ void k_slide_reduce(const __half* __restrict__ a,
                               const float* __restrict__ mask) {
    __shared__ double sdata[256];
    int tid = blockIdx.x * blockDim.x + threadIdx.x;
    double acc = 0.0;
    if (tid < SLIDE_THREADS) {
        int c = tid % NCOL;
        int chunk = tid / NCOL;
        int x = c % W;
        int y = (c / W) % 160;
        int n = c / (160 * W);
        int base = n * VOL + y * W + x;
        int z0 = chunk * CHUNK;

        float sa = 0.f;
#pragma unroll
        for (int d = -2; d <= 2; d++) {
            int zz = clampi(z0 + d, 0, 159);
            sa += __half2float(a[base + zz * PLANE]);
        }
#pragma unroll 4
        for (int j = 0; j < CHUNK; j++) {
            int z = z0 + j;
            acc += (double)(sa * sa * mask[base + z * PLANE]);
            int zn = z + 3 > 159 ? 159 : z + 3;
            int zo = z - 2 < 0 ? 0 : z - 2;
            sa += __half2float(a[base + zn * PLANE])
                - __half2float(a[base + zo * PLANE]);
        }
    }
    int t = threadIdx.x;
    sdata[t] = acc;
    __syncthreads();
    for (int s = 128; s > 0; s >>= 1) {
        if (t < s) sdata[t] += sdata[t + s];
        __syncthreads();
    }
    if (t == 0) atomicAdd(&g_acc, sdata[0]);
}

__global__ void k_finish(float* __restrict__ out) {
    out[0] = (float)(-g_acc);
}

// ---------------------------------------------------------------------------
extern "C" void kernel_launch(void* const* d_in, const int* in_sizes, int n_in,
                              void* d_out, int out_size) {
    const float* f    = (const float*)d_in[0];
    const float* m    = (const float*)d_in[1];
    const float* mask = (const float*)d_in[2];
    float* out = (float*)d_out;

    __half2* t01 = nullptr; cudaGetSymbolAddress((void**)&t01, g_t01);
    __half2* s1  = nullptr; cudaGetSymbolAddress((void**)&s1, g_s1);
    __half2* s2  = nullptr; cudaGetSymbolAddress((void**)&s2, g_s2);
    __half*  t2  = nullptr; cudaGetSymbolAddress((void**)&t2, g_t2);

    dim3 grd(W / TX, H / TY, D * NB);   // (5, 5, 320) = 8000 blocks
    const int TB = 256;
    const int gridS = (SLIDE_THREADS + TB - 1) / TB; // 1000

    k_zero_acc<<<1, 1>>>();

    // Stage 1: xy box of (F, M), then z slide -> s1
    k_xy_pair<<<grd, TB>>>(LoadRawPair{f, m}, t01);
    k_slide_pair_z<<<gridS, TB>>>(t01, s1);

    // Stage 2: xy box of ((im-u)^2 pair), then z slide -> s2
    k_xy_pair<<<grd, TB>>>(LoadGPair{f, m, s1}, t01);
    k_slide_pair_z<<<gridS, TB>>>(t01, s2);

    // Stage 3: xy box of n_F*n_M, then z slide + masked reduction
    k_xy_one<<<grd, TB>>>(LoadP{f, m, s1, s2}, t2);
    k_slide_reduce<<<gridS, TB>>>(t2, mask);

    k_finish<<<1, 1>>>(out);
    (void)in_sizes; (void)n_in; (void)out_size;
}

// round 13
// speedup vs baseline: 5.8983x; 1.1928x over previous
#include <cuda_runtime.h>
#include <cuda_fp16.h>
#include <math.h>

#define W 160
#define H 160
#define D 160
#define NB 2
#define PLANE (H * W)              // 25600
#define VOL (D * H * W)            // 4096000
#define NE (NB * VOL)              // 8192000
#define INV_SZ (1.0f / 125.0f)

// xy tile geometry
#define TX 32
#define TY 32
#define HX 36
#define HY 36

// z sliding-pass decomposition: 160 = 10 chunks of 16
#define CHUNK 16
#define NCHUNK 10
#define NCOLP (160 * 160)                 // columns per volume-pass (batch folded)
#define SLIDE_THREADS (NCOLP * NCHUNK)    // 256000

// 4-field pack: p0 = (F,M) batch0, p1 = (F,M) batch1
struct __align__(8) H4 { __half2 p0, p1; };

// Scratch (__device__ globals: allocation-free rule)
__device__ H4 g_t01[VOL];       // ping: xy-boxed 4-pack
__device__ H4 g_s1[VOL];        // 3D box of (F,M) pairs
__device__ H4 g_s2[VOL];        // 3D box of g pairs
__device__ H4 g_fm[VOL];        // cached half inputs
__device__ __half2 g_t2[VOL];   // stage-3 xy-boxed product (batch pair)
__device__ double g_acc;

__device__ __forceinline__ float frsqrt_approx(float x) {
    float y;
    asm("rsqrt.approx.f32 %0, %1;" : "=f"(y) : "f"(x));
    return y;
}
__device__ __forceinline__ int clampi(int v, int lo, int hi) {
    return v < lo ? lo : (v > hi ? hi : v);
}
__device__ __forceinline__ H4 h4add(H4 a, H4 b) {
    H4 r; r.p0 = __hadd2(a.p0, b.p0); r.p1 = __hadd2(a.p1, b.p1); return r;
}
__device__ __forceinline__ H4 h4sub(H4 a, H4 b) {
    H4 r; r.p0 = __hsub2(a.p0, b.p0); r.p1 = __hsub2(a.p1, b.p1); return r;
}
__device__ __forceinline__ float2 f2add(float2 a, float2 b) {
    return make_float2(a.x + b.x, a.y + b.y);
}
__device__ __forceinline__ float2 f2sub(float2 a, float2 b) {
    return make_float2(a.x - b.x, a.y - b.y);
}

__global__ void k_zero_acc() { g_acc = 0.0; }

// ---------------------------------------------------------------------------
// Loaders: j is the batch-0 voxel index (batch-1 lives at j + VOL).
struct LoadRaw4 {   // raw (F,M) pairs; side effect: populate half fm cache
    const float* __restrict__ f;
    const float* __restrict__ m;
    H4* __restrict__ fm;
    __device__ __forceinline__ H4 operator()(int j) const {
        H4 r;
        r.p0 = __floats2half2_rn(f[j], m[j]);
        r.p1 = __floats2half2_rn(f[j + VOL], m[j + VOL]);
        fm[j] = r;  // duplicate same-value writes at halo overlaps are benign
        return r;
    }
};
struct LoadG4 {     // (im - u)^2 per field
    const H4* __restrict__ fm;
    const H4* __restrict__ s1;
    __device__ __forceinline__ H4 operator()(int j) const {
        H4 a = fm[j], u = s1[j], r;
        float2 v0 = __half22float2(a.p0), u0 = __half22float2(u.p0);
        float2 v1 = __half22float2(a.p1), u1 = __half22float2(u.p1);
        float d0x = v0.x - u0.x * INV_SZ, d0y = v0.y - u0.y * INV_SZ;
        float d1x = v1.x - u1.x * INV_SZ, d1y = v1.y - u1.y * INV_SZ;
        r.p0 = __floats2half2_rn(d0x * d0x, d0y * d0y);
        r.p1 = __floats2half2_rn(d1x * d1x, d1y * d1y);
        return r;
    }
};
struct LoadP4 {     // n_F * n_M per batch -> half2 (b0, b1)
    const H4* __restrict__ fm;
    const H4* __restrict__ s1;
    const H4* __restrict__ s2;
    __device__ __forceinline__ __half2 operator()(int j) const {
        H4 a = fm[j], u = s1[j], v = s2[j];
        float2 a0 = __half22float2(a.p0), u0 = __half22float2(u.p0), v0 = __half22float2(v.p0);
        float2 a1 = __half22float2(a.p1), u1 = __half22float2(u.p1), v1 = __half22float2(v.p1);
        float pr0 = fmaxf((v0.x * INV_SZ) * (v0.y * INV_SZ), 1e-24f);
        float pr1 = fmaxf((v1.x * INV_SZ) * (v1.y * INV_SZ), 1e-24f);
        float p0 = (a0.x - u0.x * INV_SZ) * (a0.y - u0.y * INV_SZ) * frsqrt_approx(pr0);
        float p1 = (a1.x - u1.x * INV_SZ) * (a1.y - u1.y * INV_SZ) * frsqrt_approx(pr1);
        return __floats2half2_rn(p0, p1);
    }
};

// ---------------------------------------------------------------------------
// xy box of one 32x32 tile of one z-plane, 4 fields packed, HADD2 arithmetic.
// grid = (5, 5, D) = 4000 blocks, block = 256.
template <class L>
__global__ void __launch_bounds__(256) k_xy_pair4(L ld, H4* __restrict__ out) {
    __shared__ H4 s_in[HY][HX + 1];
    __shared__ H4 s_yr[HX][TY + 1];

    const int gx0 = blockIdx.x * TX;
    const int gy0 = blockIdx.y * TY;
    const int zp  = blockIdx.z;
    const int zbase = zp * PLANE;
    const int tid = threadIdx.x;

    // Halo load (replicate padding via clamped coords)
    for (int i = tid; i < HY * HX; i += 256) {
        int ly = i / HX;
        int lx = i - ly * HX;
        int gy = clampi(gy0 - 2 + ly, 0, H - 1);
        int gx = clampi(gx0 - 2 + lx, 0, W - 1);
        s_in[ly][lx] = ld(zbase + gy * W + gx);
    }
    __syncthreads();

    // Phase A: y-box for all 36 columns, register sliding over 4 consecutive y
    for (int g = tid; g < HX * 8; g += 256) {
        int x = g % HX;
        int y0 = (g / HX) * 4;
        H4 s = h4add(h4add(h4add(h4add(s_in[y0][x], s_in[y0 + 1][x]),
                                 s_in[y0 + 2][x]), s_in[y0 + 3][x]), s_in[y0 + 4][x]);
        s_yr[x][y0] = s;
#pragma unroll
        for (int j = 1; j < 4; j++) {
            s = h4add(s, h4sub(s_in[y0 + 4 + j][x], s_in[y0 + j - 1][x]));
            s_yr[x][y0 + j] = s;
        }
    }
    __syncthreads();

    // Phase B: x-box, 4 consecutive x per thread; warp covers 4 full rows.
    {
        int xg = tid % 8;
        int yrow = tid / 8;
        int x0 = 4 * xg;
        H4 s = h4add(h4add(h4add(h4add(s_yr[x0][yrow], s_yr[x0 + 1][yrow]),
                                 s_yr[x0 + 2][yrow]), s_yr[x0 + 3][yrow]),
                     s_yr[x0 + 4][yrow]);
        __align__(16) H4 r[4];
        r[0] = s;
#pragma unroll
        for (int j = 1; j < 4; j++) {
            s = h4add(s, h4sub(s_yr[x0 + 4 + j][yrow], s_yr[x0 + j - 1][yrow]));
            r[j] = s;
        }
        int o = zbase + (gy0 + yrow) * W + gx0 + x0;
        *reinterpret_cast<uint4*>(&out[o])     = *reinterpret_cast<uint4*>(&r[0]);
        *reinterpret_cast<uint4*>(&out[o + 2]) = *reinterpret_cast<uint4*>(&r[2]);
    }
}

// Stage-3 xy kernel: half2 (batch pair) per voxel.
template <class L>
__global__ void __launch_bounds__(256) k_xy_one4(L ld, __half2* __restrict__ out) {
    __shared__ __half2 s_in[HY][HX + 1];
    __shared__ __half2 s_yr[HX][TY + 1];

    const int gx0 = blockIdx.x * TX;
    const int gy0 = blockIdx.y * TY;
    const int zp  = blockIdx.z;
    const int zbase = zp * PLANE;
    const int tid = threadIdx.x;

    for (int i = tid; i < HY * HX; i += 256) {
        int ly = i / HX;
        int lx = i - ly * HX;
        int gy = clampi(gy0 - 2 + ly, 0, H - 1);
        int gx = clampi(gx0 - 2 + lx, 0, W - 1);
        s_in[ly][lx] = ld(zbase + gy * W + gx);
    }
    __syncthreads();

    for (int g = tid; g < HX * 8; g += 256) {
        int x = g % HX;
        int y0 = (g / HX) * 4;
        __half2 s = __hadd2(__hadd2(__hadd2(__hadd2(s_in[y0][x], s_in[y0 + 1][x]),
                                            s_in[y0 + 2][x]), s_in[y0 + 3][x]),
                            s_in[y0 + 4][x]);
        s_yr[x][y0] = s;
#pragma unroll
        for (int j = 1; j < 4; j++) {
            s = __hadd2(s, __hsub2(s_in[y0 + 4 + j][x], s_in[y0 + j - 1][x]));
            s_yr[x][y0 + j] = s;
        }
    }
    __syncthreads();

    {
        int xg = tid % 8;
        int yrow = tid / 8;
        int x0 = 4 * xg;
        __half2 s = __hadd2(__hadd2(__hadd2(__hadd2(s_yr[x0][yrow], s_yr[x0 + 1][yrow]),
                                            s_yr[x0 + 2][yrow]), s_yr[x0 + 3][yrow]),
                            s_yr[x0 + 4][yrow]);
        __align__(16) __half2 r[4];
        r[0] = s;
#pragma unroll
        for (int j = 1; j < 4; j++) {
            s = __hadd2(s, __hsub2(s_yr[x0 + 4 + j][yrow], s_yr[x0 + j - 1][yrow]));
            r[j] = s;
        }
        int o = zbase + (gy0 + yrow) * W + gx0 + x0;
        *reinterpret_cast<uint4*>(&out[o]) = *reinterpret_cast<uint4*>(r);
    }
}

// ---------------------------------------------------------------------------
// z-axis sliding 5-tap clamped sum on H4 columns (4 fields), fp32 accumulate.
__global__ void k_slide4_z(const H4* __restrict__ a, H4* __restrict__ o) {
    int tid = blockIdx.x * blockDim.x + threadIdx.x;
    if (tid >= SLIDE_THREADS) return;
    int c = tid % NCOLP;
    int chunk = tid / NCOLP;
    int base = c;               // plane index (x + y*W)
    int z0 = chunk * CHUNK;

    float2 s0 = make_float2(0.f, 0.f), s1a = make_float2(0.f, 0.f);
#pragma unroll
    for (int d = -2; d <= 2; d++) {
        int zz = clampi(z0 + d, 0, 159);
        H4 v = a[base + zz * PLANE];
        s0 = f2add(s0, __half22float2(v.p0));
        s1a = f2add(s1a, __half22float2(v.p1));
    }
#pragma unroll 4
    for (int j = 0; j < CHUNK; j++) {
        int z = z0 + j;
        H4 w;
        w.p0 = __float22half2_rn(s0);
        w.p1 = __float22half2_rn(s1a);
        o[base + z * PLANE] = w;
        int zn = z + 3 > 159 ? 159 : z + 3;
        int zo = z - 2 < 0 ? 0 : z - 2;
        H4 vn = a[base + zn * PLANE];
        H4 vo = a[base + zo * PLANE];
        s0 = f2add(s0, f2sub(__half22float2(vn.p0), __half22float2(vo.p0)));
        s1a = f2add(s1a, f2sub(__half22float2(vn.p1), __half22float2(vo.p1)));
    }
}

// Final z-pass + masked -sum(cross^2) reduction; both batches per thread.
__global__ void k_slide_reduce4(const __half2* __restrict__ a,
                                const float* __restrict__ mask) {
    __shared__ double sdata[256];
    int tid = blockIdx.x * blockDim.x + threadIdx.x;
    double acc = 0.0;
    if (tid < SLIDE_THREADS) {
        int c = tid % NCOLP;
        int chunk = tid / NCOLP;
        int base = c;
        int z0 = chunk * CHUNK;

        float2 s = make_float2(0.f, 0.f);
#pragma unroll
        for (int d = -2; d <= 2; d++) {
            int zz = clampi(z0 + d, 0, 159);
            s = f2add(s, __half22float2(a[base + zz * PLANE]));
        }
#pragma unroll 4
        for (int j = 0; j < CHUNK; j++) {
            int z = z0 + j;
            int i = base + z * PLANE;
            acc += (double)(s.x * s.x * mask[i]) + (double)(s.y * s.y * mask[i + VOL]);
            int zn = z + 3 > 159 ? 159 : z + 3;
            int zo = z - 2 < 0 ? 0 : z - 2;
            s = f2add(s, f2sub(__half22float2(a[base + zn * PLANE]),
                               __half22float2(a[base + zo * PLANE])));
        }
    }
    int t = threadIdx.x;
    sdata[t] = acc;
    __syncthreads();
    for (int sft = 128; sft > 0; sft >>= 1) {
        if (t < sft) sdata[t] += sdata[t + sft];
        __syncthreads();
    }
    if (t == 0) atomicAdd(&g_acc, sdata[0]);
}

__global__ void k_finish(float* __restrict__ out) {
    out[0] = (float)(-g_acc);
}

// ---------------------------------------------------------------------------
extern "C" void kernel_launch(void* const* d_in, const int* in_sizes, int n_in,
                              void* d_out, int out_size) {
    const float* f    = (const float*)d_in[0];
    const float* m    = (const float*)d_in[1];
    const float* mask = (const float*)d_in[2];
    float* out = (float*)d_out;

    H4* t01 = nullptr; cudaGetSymbolAddress((void**)&t01, g_t01);
    H4* s1  = nullptr; cudaGetSymbolAddress((void**)&s1, g_s1);
    H4* s2  = nullptr; cudaGetSymbolAddress((void**)&s2, g_s2);
    H4* fm  = nullptr; cudaGetSymbolAddress((void**)&fm, g_fm);
    __half2* t2 = nullptr; cudaGetSymbolAddress((void**)&t2, g_t2);

    dim3 grd(W / TX, H / TY, D);        // (5, 5, 160) = 4000 blocks
    const int TB = 256;
    const int gridS = (SLIDE_THREADS + TB - 1) / TB; // 1000

    k_zero_acc<<<1, 1>>>();

    // Stage 1: xy box of raw pairs (also fills fm cache), z slide -> s1
    k_xy_pair4<<<grd, TB>>>(LoadRaw4{f, m, fm}, t01);
    k_slide4_z<<<gridS, TB>>>(t01, s1);

    // Stage 2: xy box of (im-u)^2 pairs, z slide -> s2
    k_xy_pair4<<<grd, TB>>>(LoadG4{fm, s1}, t01);
    k_slide4_z<<<gridS, TB>>>(t01, s2);

    // Stage 3: xy box of n_F*n_M (batch pair), z slide + masked reduction
    k_xy_one4<<<grd, TB>>>(LoadP4{fm, s1, s2}, t2);
    k_slide_reduce4<<<gridS, TB>>>(t2, mask);

    k_finish<<<1, 1>>>(out);
    (void)in_sizes; (void)n_in; (void)out_size;
}